// round 8
// baseline (speedup 1.0000x reference)
#include <cuda_runtime.h>
#include <math.h>

// Problem constants
#define B    16
#define SQ   128
#define SK   256
#define HID  128
#define H    4
#define DK   32
#define DIM  64
#define OUT  128

typedef unsigned long long u64;

// ---- packed f32x2 helpers (Blackwell FFMA2; ptxas never auto-fuses) ----
__device__ __forceinline__ void ffma2(u64 &d, u64 a, u64 b) {
    asm("fma.rn.f32x2 %0, %1, %2, %3;" : "=l"(d) : "l"(a), "l"(b), "l"(d));
}
__device__ __forceinline__ u64 dup2(float x) {
    u64 r; asm("mov.b64 %0, {%1, %1};" : "=l"(r) : "f"(x)); return r;
}
__device__ __forceinline__ u64 pack2(float lo, float hi) {
    u64 r; asm("mov.b64 %0, {%1, %2};" : "=l"(r) : "f"(lo), "f"(hi)); return r;
}
__device__ __forceinline__ float2 unpack2(u64 v) {
    float2 f; asm("mov.b64 {%0, %1}, %2;" : "=f"(f.x), "=f"(f.y) : "l"(v)); return f;
}

// Intermediate scratch (no cudaMalloc allowed)
__device__ float g_qp[B * SQ * HID];
__device__ float g_kp[B * SK * HID];
__device__ float g_x [B * SQ * (H * DIM)];

// ---------------------------------------------------------------------------
// QK projection GEMM: C[M,128] = A[M,128] @ W[128,128]^T + bias
// 32x64 tile, 128 threads, 4m x 4n per thread, acc pairs along n.
// As stores DUPLICATED a: As[k][2m]={a,a} -> inner loop has no MOVs:
//   2 LDS.128 (dup'd a, broadcast) + 1 LDS.128 (b pairs) + 8 FFMA2 per 16 MAC.
// ---------------------------------------------------------------------------
#define PAD 68   // As pitch in floats (64 dup'd + 4 pad)
#define PBS 68   // Bs pitch in floats

__global__ __launch_bounds__(128) void qk_proj_kernel(
        const float* __restrict__ q,  const float* __restrict__ Wq,
        const float* __restrict__ bq, float* __restrict__ qp,
        const float* __restrict__ k,  const float* __restrict__ Wk,
        const float* __restrict__ bk, float* __restrict__ kp) {
    extern __shared__ float sm[];
    float* As = sm;                 // 128 * PAD (dup'd)
    float* Bs = sm + 128 * PAD;     // 128 * PBS
    const int t = threadIdx.x;

    const float *A, *W, *bias; float* C; int tile;
    if (blockIdx.x < 128) { A = q; W = Wq; bias = bq; C = qp; tile = blockIdx.x; }
    else                  { A = k; W = Wk; bias = bk; C = kp; tile = blockIdx.x - 128; }
    const int row0 = (tile >> 1) * 32;
    const int col0 = (tile & 1) * 64;

    // stage A (32 rows x 128 k) transposed + duplicated -> As[k][{a,a}...]
    {
        const int lm = t >> 2, kb = (t & 3) * 32;
        #pragma unroll
        for (int j = 0; j < 8; j++) {
            float4 v = *(const float4*)(A + (row0 + lm) * 128 + kb + j * 4);
            *(u64*)(As + (kb + j * 4 + 0) * PAD + lm * 2) = dup2(v.x);
            *(u64*)(As + (kb + j * 4 + 1) * PAD + lm * 2) = dup2(v.y);
            *(u64*)(As + (kb + j * 4 + 2) * PAD + lm * 2) = dup2(v.z);
            *(u64*)(As + (kb + j * 4 + 3) * PAD + lm * 2) = dup2(v.w);
        }
    }
    // stage W (64 n x 128 k) transposed -> Bs[k][n]
    {
        const int n = t >> 1, kb = (t & 1) * 64;
        #pragma unroll
        for (int j = 0; j < 16; j++) {
            float4 v = *(const float4*)(W + (col0 + n) * 128 + kb + j * 4);
            Bs[(kb + j * 4 + 0) * PBS + n] = v.x;
            Bs[(kb + j * 4 + 1) * PBS + n] = v.y;
            Bs[(kb + j * 4 + 2) * PBS + n] = v.z;
            Bs[(kb + j * 4 + 3) * PBS + n] = v.w;
        }
    }
    __syncthreads();

    const int ty = t >> 4;          // 0..7 -> rows ty*4..+3 (dup offset ty*8)
    const int tx = t & 15;          // 0..15 -> cols tx*4..+3
    u64 acc[4][2];
    #pragma unroll
    for (int i = 0; i < 4; i++) { acc[i][0] = 0ull; acc[i][1] = 0ull; }

    #pragma unroll 8
    for (int kk = 0; kk < 128; kk++) {
        ulonglong2 a01 = *(const ulonglong2*)(As + kk * PAD + ty * 8);      // {a0,a0},{a1,a1}
        ulonglong2 a23 = *(const ulonglong2*)(As + kk * PAD + ty * 8 + 4);  // {a2,a2},{a3,a3}
        ulonglong2 bb  = *(const ulonglong2*)(Bs + kk * PBS + tx * 4);      // {b0,b1},{b2,b3}
        ffma2(acc[0][0], a01.x, bb.x); ffma2(acc[0][1], a01.x, bb.y);
        ffma2(acc[1][0], a01.y, bb.x); ffma2(acc[1][1], a01.y, bb.y);
        ffma2(acc[2][0], a23.x, bb.x); ffma2(acc[2][1], a23.x, bb.y);
        ffma2(acc[3][0], a23.y, bb.x); ffma2(acc[3][1], a23.y, bb.y);
    }

    const float4 bias4 = *(const float4*)(bias + col0 + tx * 4);
    #pragma unroll
    for (int i = 0; i < 4; i++) {
        float2 p0 = unpack2(acc[i][0]);
        float2 p1 = unpack2(acc[i][1]);
        float4 o;
        o.x = p0.x + bias4.x; o.y = p0.y + bias4.y;
        o.z = p1.x + bias4.z; o.w = p1.y + bias4.w;
        *(float4*)(C + (row0 + ty * 4 + i) * 128 + col0 + tx * 4) = o;
    }
}

// ---------------------------------------------------------------------------
// O projection GEMM: out[2048,128] = x[2048,256] @ Wo[128,256]^T + bo
// 16x64 tiles -> 256 blocks, 128 threads, 2m x 4n, acc pairs along n.
// As duplicated (pitch 36), K=256 staged in two 128-k chunks.
// ---------------------------------------------------------------------------
#define PAO 36   // As pitch: 32 dup'd + 4 pad

__global__ __launch_bounds__(128) void o_proj_kernel(
        const float* __restrict__ x,  const float* __restrict__ Wo,
        const float* __restrict__ bo, float* __restrict__ out) {
    extern __shared__ float sm[];
    float* As = sm;                 // 128 * PAO
    float* Bs = sm + 128 * PAO;     // 128 * PBS
    const int t = threadIdx.x;
    const int row0 = (blockIdx.x >> 1) * 16;
    const int col0 = (blockIdx.x & 1) * 64;
    const int ty = t >> 4;          // 0..7 -> rows ty*2..+1 (dup offset ty*4)
    const int tx = t & 15;          // cols tx*4..+3

    u64 acc[2][2] = {{0ull, 0ull}, {0ull, 0ull}};

    #pragma unroll 1
    for (int kc = 0; kc < 2; kc++) {
        if (kc) __syncthreads();
        // stage A chunk (16 rows x 128 k) dup'd -> As[k][{a,a}...]
        {
            const int lm = t >> 3, kb = (t & 7) * 16;
            #pragma unroll
            for (int j = 0; j < 4; j++) {
                float4 v = *(const float4*)(x + (row0 + lm) * 256 + kc * 128 + kb + j * 4);
                *(u64*)(As + (kb + j * 4 + 0) * PAO + lm * 2) = dup2(v.x);
                *(u64*)(As + (kb + j * 4 + 1) * PAO + lm * 2) = dup2(v.y);
                *(u64*)(As + (kb + j * 4 + 2) * PAO + lm * 2) = dup2(v.z);
                *(u64*)(As + (kb + j * 4 + 3) * PAO + lm * 2) = dup2(v.w);
            }
        }
        // stage W chunk (64 n x 128 k) -> Bs[k][n]
        {
            const int n = t >> 1, kb = (t & 1) * 64;
            #pragma unroll
            for (int j = 0; j < 16; j++) {
                float4 v = *(const float4*)(Wo + (col0 + n) * 256 + kc * 128 + kb + j * 4);
                Bs[(kb + j * 4 + 0) * PBS + n] = v.x;
                Bs[(kb + j * 4 + 1) * PBS + n] = v.y;
                Bs[(kb + j * 4 + 2) * PBS + n] = v.z;
                Bs[(kb + j * 4 + 3) * PBS + n] = v.w;
            }
        }
        __syncthreads();

        #pragma unroll 8
        for (int kk = 0; kk < 128; kk++) {
            ulonglong2 aa = *(const ulonglong2*)(As + kk * PAO + ty * 4); // {a0,a0},{a1,a1}
            ulonglong2 bb = *(const ulonglong2*)(Bs + kk * PBS + tx * 4); // {b0,b1},{b2,b3}
            ffma2(acc[0][0], aa.x, bb.x); ffma2(acc[0][1], aa.x, bb.y);
            ffma2(acc[1][0], aa.y, bb.x); ffma2(acc[1][1], aa.y, bb.y);
        }
    }

    const float4 bias4 = *(const float4*)(bo + col0 + tx * 4);
    #pragma unroll
    for (int i = 0; i < 2; i++) {
        float2 p0 = unpack2(acc[i][0]);
        float2 p1 = unpack2(acc[i][1]);
        float4 o;
        o.x = p0.x + bias4.x; o.y = p0.y + bias4.y;
        o.z = p1.x + bias4.z; o.w = p1.y + bias4.w;
        *(float4*)(out + (row0 + ty * 2 + i) * 128 + col0 + tx * 4) = o;
    }
}

// ---------------------------------------------------------------------------
// Fused masked attention. Grid: B*H*(SQ/32) = 256 blocks, 128 threads.
// Phase 1: e[k][q] = exp(q.k / sqrt(DK)) stored DUPLICATED {e,e} (pitch 68).
// Phase 2: warp owns 8 q rows, lane owns d-pair; inner loop per k:
//   4 broadcast LDS.128 (dup'd e) + 1 LDS.128 (vm) + 16 FFMA2 = 32 MAC.
// ---------------------------------------------------------------------------
#define QT 32
#define EP 68    // e_t pitch [k][2*QT + pad]
#define KP 36    // staged K pitch

__global__ __launch_bounds__(128) void attn_kernel(
        const float* __restrict__ qp,
        const float* __restrict__ kp,
        const float* __restrict__ value,
        const int*   __restrict__ mask,
        float* __restrict__ xout) {
    extern __shared__ float sm[];
    float* q_s = sm;                        // 32*32 = 1024
    float* e_t = sm + QT * 32;              // 256*68 = 17408 (dup'd, k-major)
    float* buf = e_t + SK * EP;             // 256*36 = 9216 (k-tile, then vm)
    float4* vm4 = (float4*)buf;             // phase-2 view: [64][32] float4 (8192 f)

    const int blk = blockIdx.x;
    const int qt  = blk & 3;
    const int h   = (blk >> 2) & 3;
    const int b   = blk >> 4;
    const int q0  = qt * QT;
    const int tid = threadIdx.x;

    // stage Q tile (head slice)
    for (int idx = tid; idx < QT * 32; idx += 128) {
        int r = idx >> 5, i = idx & 31;
        q_s[idx] = qp[(b * SQ + q0 + r) * HID + h * DK + i];
    }
    // stage K tile, pitch 36
    for (int idx = tid; idx < SK * 32; idx += 128) {
        int kk = idx >> 5, i = idx & 31;
        buf[kk * KP + i] = kp[(b * SK + kk) * HID + h * DK + i];
    }
    __syncthreads();

    // Phase 1: each thread handles 2 k-columns -> e_t[k][{e,e}...]
    {
        const float scale = 0.17677669529663687f;   // 1/sqrt(32)
        #pragma unroll
        for (int half = 0; half < 2; half++) {
            const int kk = tid + half * 128;
            u64 k2[16];
            #pragma unroll
            for (int i = 0; i < 8; i++) {
                float4 v = *(const float4*)(buf + kk * KP + i * 4);
                k2[i * 2 + 0] = pack2(v.x, v.y);
                k2[i * 2 + 1] = pack2(v.z, v.w);
            }
            #pragma unroll 4
            for (int r = 0; r < QT; r++) {
                u64 acc2 = 0ull;
                #pragma unroll
                for (int i = 0; i < 16; i++) {
                    u64 q2 = *(const u64*)(q_s + r * 32 + i * 2);   // broadcast
                    ffma2(acc2, q2, k2[i]);
                }
                float2 s = unpack2(acc2);
                float e = __expf((s.x + s.y) * scale);
                *(u64*)(e_t + kk * EP + r * 2) = dup2(e);
            }
        }
    }

    // Phase 2: warp w owns q rows w*8..w*8+7; lane dx owns d-pair
    const int w  = tid >> 5;   // 0..3
    const int dx = tid & 31;
    u64 acc[8][2];
    #pragma unroll
    for (int i = 0; i < 8; i++) { acc[i][0] = 0ull; acc[i][1] = 0ull; }

    #pragma unroll 1
    for (int c = 0; c < 4; c++) {
        __syncthreads();                    // phase-1 buf reads / prev chunk consumed
        // stage vm chunk: 64 k x 32 d-pairs, float4 = (mv0, m0, mv1, m1)
        #pragma unroll
        for (int it = 0; it < 16; it++) {
            int item = tid + it * 128;      // 0..2047
            int lk = item >> 5, d2 = item & 31;
            int gbase = (b * SK + c * 64 + lk) * DIM + d2 * 2;
            float2 v = *(const float2*)(value + gbase);
            int2  mm = *(const int2*)(mask + gbase);
            float4 vw;
            vw.x = mm.x ? v.x : 0.f;  vw.y = mm.x ? 1.f : 0.f;
            vw.z = mm.y ? v.y : 0.f;  vw.w = mm.y ? 1.f : 0.f;
            vm4[lk * 32 + d2] = vw;
        }
        __syncthreads();

        #pragma unroll 4
        for (int kk = 0; kk < 64; kk++) {
            const float* ebase = e_t + (c * 64 + kk) * EP + w * 16;
            ulonglong2 e01 = *(const ulonglong2*)(ebase);       // {e0,e0},{e1,e1}
            ulonglong2 e23 = *(const ulonglong2*)(ebase + 4);
            ulonglong2 e45 = *(const ulonglong2*)(ebase + 8);
            ulonglong2 e67 = *(const ulonglong2*)(ebase + 12);
            ulonglong2 wv  = *(const ulonglong2*)(vm4 + kk * 32 + dx); // {mv0,m0},{mv1,m1}
            ffma2(acc[0][0], e01.x, wv.x); ffma2(acc[0][1], e01.x, wv.y);
            ffma2(acc[1][0], e01.y, wv.x); ffma2(acc[1][1], e01.y, wv.y);
            ffma2(acc[2][0], e23.x, wv.x); ffma2(acc[2][1], e23.x, wv.y);
            ffma2(acc[3][0], e23.y, wv.x); ffma2(acc[3][1], e23.y, wv.y);
            ffma2(acc[4][0], e45.x, wv.x); ffma2(acc[4][1], e45.x, wv.y);
            ffma2(acc[5][0], e45.y, wv.x); ffma2(acc[5][1], e45.y, wv.y);
            ffma2(acc[6][0], e67.x, wv.x); ffma2(acc[6][1], e67.x, wv.y);
            ffma2(acc[7][0], e67.y, wv.x); ffma2(acc[7][1], e67.y, wv.y);
        }
    }

    // epilogue: x = num/den (den==0 fallback: mean(value))
    float num[8][2], den[8][2];
    bool bad = false;
    #pragma unroll
    for (int i = 0; i < 8; i++) {
        float2 p = unpack2(acc[i][0]); num[i][0] = p.x; den[i][0] = p.y;
        p = unpack2(acc[i][1]);        num[i][1] = p.x; den[i][1] = p.y;
        if (den[i][0] == 0.f || den[i][1] == 0.f) bad = true;
    }
    float vs0 = 0.f, vs1 = 0.f;
    if (bad) {
        for (int kk = 0; kk < SK; kk++) {
            float2 v = *(const float2*)(value + (b * SK + kk) * DIM + dx * 2);
            vs0 += v.x; vs1 += v.y;
        }
        vs0 *= (1.0f / 256.0f); vs1 *= (1.0f / 256.0f);
    }

    #pragma unroll
    for (int i = 0; i < 8; i++) {
        int r = w * 8 + i;
        float2 o;
        o.x = (den[i][0] > 0.f) ? (num[i][0] / den[i][0]) : vs0;
        o.y = (den[i][1] > 0.f) ? (num[i][1] / den[i][1]) : vs1;
        *(float2*)(xout + (b * SQ + q0 + r) * (H * DIM) + h * DIM + dx * 2) = o;
    }
}

// ---------------------------------------------------------------------------
extern "C" void kernel_launch(void* const* d_in, const int* in_sizes, int n_in,
                              void* d_out, int out_size) {
    const float* query = (const float*)d_in[0];
    const float* key   = (const float*)d_in[1];
    const float* value = (const float*)d_in[2];
    const int*   mask  = (const int*)  d_in[3];
    const float* Wq    = (const float*)d_in[4];
    const float* bq    = (const float*)d_in[5];
    const float* Wk    = (const float*)d_in[6];
    const float* bk    = (const float*)d_in[7];
    const float* Wo    = (const float*)d_in[8];
    const float* bo    = (const float*)d_in[9];
    float* out = (float*)d_out;

    float* qp; cudaGetSymbolAddress((void**)&qp, g_qp);
    float* kp; cudaGetSymbolAddress((void**)&kp, g_kp);
    float* xb; cudaGetSymbolAddress((void**)&xb, g_x);

    const int smem_qk   = (128 * PAD + 128 * PBS) * (int)sizeof(float);       // 69.6 KB
    const int smem_o    = (128 * PAO + 128 * PBS) * (int)sizeof(float);       // 53.2 KB
    const int smem_attn = (QT * 32 + SK * EP + SK * KP) * (int)sizeof(float); // 110.6 KB

    cudaFuncSetAttribute(qk_proj_kernel, cudaFuncAttributeMaxDynamicSharedMemorySize, smem_qk);
    cudaFuncSetAttribute(o_proj_kernel,  cudaFuncAttributeMaxDynamicSharedMemorySize, smem_o);
    cudaFuncSetAttribute(attn_kernel,    cudaFuncAttributeMaxDynamicSharedMemorySize, smem_attn);

    // Q (2048x128x128) + K (4096x128x128) projection: 384 blocks
    qk_proj_kernel<<<384, 128, smem_qk>>>(query, Wq, bq, qp, key, Wk, bk, kp);
    // fused attention: 256 blocks
    attn_kernel<<<B * H * (SQ / QT), 128, smem_attn>>>(qp, kp, value, mask, xb);
    // output projection: 2048x128x256, 256 blocks
    o_proj_kernel<<<256, 128, smem_o>>>(xb, Wo, bo, out);
}

// round 9
// speedup vs baseline: 1.3492x; 1.3492x over previous
#include <cuda_runtime.h>
#include <math.h>

// Problem constants
#define B    16
#define SQ   128
#define SK   256
#define HID  128
#define H    4
#define DK   32
#define DIM  64
#define OUT  128

// Intermediate scratch (no cudaMalloc allowed)
__device__ float g_qp[B * SQ * HID];
__device__ float g_kp[B * SK * HID];
__device__ float g_x [B * SQ * (H * DIM)];

// ---- tf32 helpers ----
__device__ __forceinline__ float tf32f(float x) {
    unsigned u;
    asm("cvt.rna.tf32.f32 %0, %1;" : "=r"(u) : "f"(x));
    return __uint_as_float(u);
}
__device__ __forceinline__ void mma_tf32(float* d, const unsigned* a, const unsigned* b) {
    asm volatile(
        "mma.sync.aligned.m16n8k8.row.col.f32.tf32.tf32.f32 "
        "{%0,%1,%2,%3}, {%4,%5,%6,%7}, {%8,%9}, {%0,%1,%2,%3};"
        : "+f"(d[0]), "+f"(d[1]), "+f"(d[2]), "+f"(d[3])
        : "r"(a[0]), "r"(a[1]), "r"(a[2]), "r"(a[3]), "r"(b[0]), "r"(b[1]));
}

// ---------------------------------------------------------------------------
// Register-blocked GEMM (R4 baseline, measured-best): C[M,128]=A@W^T+bias
// Block tile 32x64, 128 threads, 4x4 per thread.
// ---------------------------------------------------------------------------
template<int KDIM>
__device__ __forceinline__ void gemm_body(const float* __restrict__ A,
                                          const float* __restrict__ W,
                                          const float* __restrict__ bias,
                                          float* __restrict__ C,
                                          int tile, float* As, float* Bs) {
    const int t  = threadIdx.x;      // 0..127
    const int ty = t >> 4;           // 0..7  -> rows ty*4..+3
    const int tx = t & 15;           // 0..15 -> cols tx*4..+3
    const int row0 = (tile >> 1) * 32;
    const int col0 = (tile & 1) * 64;

    const float4 bias4 = *(const float4*)(bias + col0 + tx * 4);

    float acc[4][4];
    #pragma unroll
    for (int i = 0; i < 4; i++)
        #pragma unroll
        for (int j = 0; j < 4; j++) acc[i][j] = 0.f;

    const int lmA = t >> 2;          // 0..31
    const int lkA = (t & 3) * 4;     // 0,4,8,12
    const int lnB = t >> 1;          // 0..63
    const int lkB = (t & 1) * 8;     // 0,8

    for (int kt = 0; kt < KDIM / 16; kt++) {
        float4 av = *(const float4*)(A + (row0 + lmA) * KDIM + kt * 16 + lkA);
        As[(lkA + 0) * 32 + lmA] = av.x;
        As[(lkA + 1) * 32 + lmA] = av.y;
        As[(lkA + 2) * 32 + lmA] = av.z;
        As[(lkA + 3) * 32 + lmA] = av.w;
        float4 b0 = *(const float4*)(W + (col0 + lnB) * KDIM + kt * 16 + lkB);
        float4 b1 = *(const float4*)(W + (col0 + lnB) * KDIM + kt * 16 + lkB + 4);
        Bs[(lkB + 0) * 64 + lnB] = b0.x;
        Bs[(lkB + 1) * 64 + lnB] = b0.y;
        Bs[(lkB + 2) * 64 + lnB] = b0.z;
        Bs[(lkB + 3) * 64 + lnB] = b0.w;
        Bs[(lkB + 4) * 64 + lnB] = b1.x;
        Bs[(lkB + 5) * 64 + lnB] = b1.y;
        Bs[(lkB + 6) * 64 + lnB] = b1.z;
        Bs[(lkB + 7) * 64 + lnB] = b1.w;
        __syncthreads();

        #pragma unroll
        for (int kk = 0; kk < 16; kk++) {
            float4 a = *(const float4*)(As + kk * 32 + ty * 4);
            float4 b = *(const float4*)(Bs + kk * 64 + tx * 4);
            acc[0][0] = fmaf(a.x, b.x, acc[0][0]);
            acc[0][1] = fmaf(a.x, b.y, acc[0][1]);
            acc[0][2] = fmaf(a.x, b.z, acc[0][2]);
            acc[0][3] = fmaf(a.x, b.w, acc[0][3]);
            acc[1][0] = fmaf(a.y, b.x, acc[1][0]);
            acc[1][1] = fmaf(a.y, b.y, acc[1][1]);
            acc[1][2] = fmaf(a.y, b.z, acc[1][2]);
            acc[1][3] = fmaf(a.y, b.w, acc[1][3]);
            acc[2][0] = fmaf(a.z, b.x, acc[2][0]);
            acc[2][1] = fmaf(a.z, b.y, acc[2][1]);
            acc[2][2] = fmaf(a.z, b.z, acc[2][2]);
            acc[2][3] = fmaf(a.z, b.w, acc[2][3]);
            acc[3][0] = fmaf(a.w, b.x, acc[3][0]);
            acc[3][1] = fmaf(a.w, b.y, acc[3][1]);
            acc[3][2] = fmaf(a.w, b.z, acc[3][2]);
            acc[3][3] = fmaf(a.w, b.w, acc[3][3]);
        }
        __syncthreads();
    }

    #pragma unroll
    for (int i = 0; i < 4; i++) {
        float4 o;
        o.x = acc[i][0] + bias4.x;
        o.y = acc[i][1] + bias4.y;
        o.z = acc[i][2] + bias4.z;
        o.w = acc[i][3] + bias4.w;
        *(float4*)(C + (row0 + ty * 4 + i) * 128 + col0 + tx * 4) = o;
    }
}

__global__ __launch_bounds__(128) void qk_proj_kernel(
        const float* __restrict__ q,  const float* __restrict__ Wq,
        const float* __restrict__ bq, float* __restrict__ qp,
        const float* __restrict__ k,  const float* __restrict__ Wk,
        const float* __restrict__ bk, float* __restrict__ kp) {
    __shared__ float As[16 * 32];
    __shared__ float Bs[16 * 64];
    if (blockIdx.x < 128)
        gemm_body<128>(q, Wq, bq, qp, blockIdx.x, As, Bs);
    else
        gemm_body<128>(k, Wk, bk, kp, blockIdx.x - 128, As, Bs);
}

__global__ __launch_bounds__(128) void o_proj_kernel(
        const float* __restrict__ x,  const float* __restrict__ Wo,
        const float* __restrict__ bo, float* __restrict__ out) {
    __shared__ float As[16 * 32];
    __shared__ float Bs[16 * 64];
    gemm_body<256>(x, Wo, bo, out, blockIdx.x, As, Bs);
}

// ---------------------------------------------------------------------------
// Fused masked attention. Grid: B*H*(SQ/32) = 256 blocks, 256 threads.
// Phase 1 (SIMT fp32): e[k][q] = exp(q.k/sqrt(DK)), tf32-rounded, pitch 36.
// Phase 2 (tf32 mma.sync m16n8k8):
//   D[32q x 128n] += e[32q x 256k] @ vm[256k x 128n]
//   where n = interleaved columns (2d = mask*value, 2d+1 = mask), so each
//   thread's (c0,c1) = (num,den) for one channel. vm staged per 64-k chunk
//   at pitch 132 (conflict-free B-fragment loads).
// ---------------------------------------------------------------------------
#define QT 32
#define EP 36    // e_t pitch [k][q]
#define KP 33    // staged K pitch (phase 1)
#define VP 132   // vm pitch [k][n]

__global__ __launch_bounds__(256) void attn_kernel(
        const float* __restrict__ qp,
        const float* __restrict__ kp,
        const float* __restrict__ value,
        const int*   __restrict__ mask,
        float* __restrict__ xout) {
    extern __shared__ float sm[];
    float* q_s = sm;                        // 32*32  = 1024
    float* e_t = sm + QT * 32;              // 256*36 = 9216
    float* buf = e_t + SK * EP;             // 256*33 = 8448 (K tile, then vm 64*132=8448)

    const int blk = blockIdx.x;
    const int qt  = blk & 3;
    const int h   = (blk >> 2) & 3;
    const int b   = blk >> 4;
    const int q0  = qt * QT;
    const int tid = threadIdx.x;

    // stage Q tile (head slice)
    for (int idx = tid; idx < QT * 32; idx += 256) {
        int r = idx >> 5, i = idx & 31;
        q_s[idx] = qp[(b * SQ + q0 + r) * HID + h * DK + i];
    }
    // stage K tile, pitch 33
    for (int idx = tid; idx < SK * 32; idx += 256) {
        int kk = idx >> 5, i = idx & 31;
        buf[kk * KP + i] = kp[(b * SK + kk) * HID + h * DK + i];
    }
    __syncthreads();

    // Phase 1: one thread per k column -> e_t[k][q] (tf32-rounded)
    {
        const int kk = tid;
        float kreg[32];
        #pragma unroll
        for (int i = 0; i < 32; i++) kreg[i] = buf[kk * KP + i];
        const float scale = 0.17677669529663687f;   // 1/sqrt(32)
        #pragma unroll 4
        for (int r = 0; r < QT; r++) {
            float acc = 0.f;
            #pragma unroll
            for (int i = 0; i < 32; i++)
                acc = fmaf(q_s[r * 32 + i], kreg[i], acc);
            e_t[kk * EP + r] = tf32f(__expf(acc * scale));
        }
    }

    // Phase 2: tf32 MMA. 8 warps; warp w covers n-cols [w*16, w*16+16).
    const int lane = tid & 31;
    const int w    = tid >> 5;
    const int lr   = lane >> 2;   // 0..7
    const int lc   = lane & 3;    // 0..3
    const int nb   = w * 16;

    float d[2][2][4];
    #pragma unroll
    for (int i = 0; i < 2; i++)
        #pragma unroll
        for (int j = 0; j < 2; j++)
            #pragma unroll
            for (int r = 0; r < 4; r++) d[i][j][r] = 0.f;

    const unsigned* eu = (const unsigned*)e_t;
    const unsigned* vu = (const unsigned*)buf;

    #pragma unroll 1
    for (int c = 0; c < 4; c++) {
        __syncthreads();                    // phase-1 buf reads / prev chunk consumed
        // stage vm chunk: 64 k-rows x 128 n-cols, float4 per d-pair
        #pragma unroll
        for (int it = 0; it < 8; it++) {
            int item = tid + it * 256;      // 0..2047
            int lk = item >> 5, d2 = item & 31;
            int gbase = (b * SK + c * 64 + lk) * DIM + d2 * 2;
            float2 v = *(const float2*)(value + gbase);
            int2  mm = *(const int2*)(mask + gbase);
            float4 wv;
            wv.x = mm.x ? tf32f(v.x) : 0.f;  wv.y = mm.x ? 1.f : 0.f;
            wv.z = mm.y ? tf32f(v.y) : 0.f;  wv.w = mm.y ? 1.f : 0.f;
            *(float4*)(buf + lk * VP + d2 * 4) = wv;
        }
        __syncthreads();

        #pragma unroll
        for (int ks = 0; ks < 8; ks++) {
            const int k0 = c * 64 + ks * 8;
            // A fragments (e), shared across n-tiles
            unsigned a[2][4];
            const int ea = (k0 + lc) * EP + lr;
            const int eb = (k0 + 4 + lc) * EP + lr;
            #pragma unroll
            for (int i = 0; i < 2; i++) {
                a[i][0] = eu[ea + i * 16];
                a[i][1] = eu[ea + i * 16 + 8];
                a[i][2] = eu[eb + i * 16];
                a[i][3] = eu[eb + i * 16 + 8];
            }
            // B fragments (vm)
            unsigned bf[2][2];
            const int ba = (ks * 8 + lc) * VP + nb + lr;
            #pragma unroll
            for (int j = 0; j < 2; j++) {
                bf[j][0] = vu[ba + j * 8];
                bf[j][1] = vu[ba + j * 8 + 4 * VP];
            }
            #pragma unroll
            for (int i = 0; i < 2; i++)
                #pragma unroll
                for (int j = 0; j < 2; j++)
                    mma_tf32(d[i][j], a[i], bf[j]);
        }
    }

    // Epilogue: x = num/den. Thread holds (num,den) adjacent per channel.
    #pragma unroll
    for (int j = 0; j < 2; j++) {
        const int ch = w * 8 + j * 4 + lc;          // d channel
        // fallback mean(value) if a den is zero (all-masked channel)
        bool bad = false;
        #pragma unroll
        for (int i = 0; i < 2; i++)
            if (d[i][j][1] == 0.f || d[i][j][3] == 0.f) bad = true;
        float vs = 0.f;
        if (bad) {
            for (int kk = 0; kk < SK; kk++)
                vs += value[(b * SK + kk) * DIM + ch];
            vs *= (1.0f / 256.0f);
        }
        #pragma unroll
        for (int i = 0; i < 2; i++) {
            const int ra = i * 16 + lr;
            const int rb = ra + 8;
            float xa = (d[i][j][1] > 0.f) ? (d[i][j][0] / d[i][j][1]) : vs;
            float xb = (d[i][j][3] > 0.f) ? (d[i][j][2] / d[i][j][3]) : vs;
            xout[(b * SQ + q0 + ra) * (H * DIM) + h * DIM + ch] = xa;
            xout[(b * SQ + q0 + rb) * (H * DIM) + h * DIM + ch] = xb;
        }
    }
}

// ---------------------------------------------------------------------------
extern "C" void kernel_launch(void* const* d_in, const int* in_sizes, int n_in,
                              void* d_out, int out_size) {
    const float* query = (const float*)d_in[0];
    const float* key   = (const float*)d_in[1];
    const float* value = (const float*)d_in[2];
    const int*   mask  = (const int*)  d_in[3];
    const float* Wq    = (const float*)d_in[4];
    const float* bq    = (const float*)d_in[5];
    const float* Wk    = (const float*)d_in[6];
    const float* bk    = (const float*)d_in[7];
    const float* Wo    = (const float*)d_in[8];
    const float* bo    = (const float*)d_in[9];
    float* out = (float*)d_out;

    float* qp; cudaGetSymbolAddress((void**)&qp, g_qp);
    float* kp; cudaGetSymbolAddress((void**)&kp, g_kp);
    float* xb; cudaGetSymbolAddress((void**)&xb, g_x);

    const int smem_attn = (QT * 32 + SK * EP + SK * KP) * (int)sizeof(float); // ~74.8KB
    cudaFuncSetAttribute(attn_kernel, cudaFuncAttributeMaxDynamicSharedMemorySize, smem_attn);

    // Q (2048x128x128) + K (4096x128x128) projection: 384 blocks
    qk_proj_kernel<<<384, 128>>>(query, Wq, bq, qp, key, Wk, bk, kp);
    // fused attention: 256 blocks
    attn_kernel<<<B * H * (SQ / QT), 256, smem_attn>>>(qp, kp, value, mask, xb);
    // output projection: 2048x128x256
    o_proj_kernel<<<128, 128>>>(xb, Wo, bo, out);
}